// round 9
// baseline (speedup 1.0000x reference)
#include <cuda_runtime.h>
#include <cuda_bf16.h>
#include <stdint.h>
#include <string.h>

#define BATCH  512
#define NTOK   1024
#define DDIM   128
#define NCHUNK 8
#define NOUT   1023
#define NTHR   512

// ---------------- smem layout (bytes) ----------------
#define S_A0HI 0              // 32768 each: A/H1 bf16 [128 rows][256B], XOR swizzle
#define S_A0LO 32768
#define S_A1HI 65536
#define S_A1LO 98304
#define S_W1HI 131072         // 32768
#define S_W1LO 163840         // 32768
#define S_W2HI 196608         // 16384
#define S_W2LO 212992         // 16384
#define S_SCR  229376         // 2048: TOT -> OFF (in place) -> PT (aliased phases)
#define S_B2   231424         // 256
#define S_W3   231680         // 256
#define S_B3   231936         // 16
#define SMEM_BYTES 231952

static __device__ __forceinline__ uint32_t smem_u32(const void* p) {
    uint32_t a;
    asm("{ .reg .u64 t; cvta.to.shared.u64 t, %1; cvt.u32.u64 %0, t; }"
        : "=r"(a) : "l"(p));
    return a;
}
static __device__ __forceinline__ uint32_t tswz(uint32_t row, uint32_t cb) {
    return row * 256 + (cb ^ ((row & 7) << 4));
}
static __device__ __forceinline__ float bfr(float v) {
    return __bfloat162float(__float2bfloat16(v));
}
static __device__ __forceinline__ uint32_t pack2(float a, float b) {
    __nv_bfloat162 h = __floats2bfloat162_rn(a, b);
    uint32_t u;
    memcpy(&u, &h, 4);
    return u;
}
static __device__ __forceinline__ float lrelu(float v) {
    return v > 0.f ? v : 0.01f * v;
}
static __device__ __forceinline__ void ldm4(uint32_t addr, uint32_t& r0, uint32_t& r1,
                                            uint32_t& r2, uint32_t& r3) {
    asm volatile("ldmatrix.sync.aligned.m8n8.x4.shared.b16 {%0,%1,%2,%3}, [%4];"
                 : "=r"(r0), "=r"(r1), "=r"(r2), "=r"(r3) : "r"(addr));
}
static __device__ __forceinline__ void mma16816(float* d, uint32_t a0, uint32_t a1,
                                                uint32_t a2, uint32_t a3,
                                                uint32_t b0, uint32_t b1) {
    asm volatile("mma.sync.aligned.m16n8k16.row.col.f32.bf16.bf16.f32 "
                 "{%0,%1,%2,%3}, {%4,%5,%6,%7}, {%8,%9}, {%0,%1,%2,%3};"
                 : "+f"(d[0]), "+f"(d[1]), "+f"(d[2]), "+f"(d[3])
                 : "r"(a0), "r"(a1), "r"(a2), "r"(a3), "r"(b0), "r"(b1));
}
static __device__ __forceinline__ void scan_col(float& lo, float& hi, int lane) {
    float o;
    o = __shfl_up_sync(0xffffffffu, lo, 4);  if (lane >= 4)  lo += o;
    o = __shfl_up_sync(0xffffffffu, lo, 8);  if (lane >= 8)  lo += o;
    o = __shfl_up_sync(0xffffffffu, lo, 16); if (lane >= 16) lo += o;
    float tl = __shfl_sync(0xffffffffu, lo, 28 + (lane & 3));
    o = __shfl_up_sync(0xffffffffu, hi, 4);  if (lane >= 4)  hi += o;
    o = __shfl_up_sync(0xffffffffu, hi, 8);  if (lane >= 8)  hi += o;
    o = __shfl_up_sync(0xffffffffu, hi, 16); if (lane >= 16) hi += o;
    hi += tl;
}
// convert one float4 of x (float4 index idx in [0,4096)) into bf16 hi/lo tiles
static __device__ __forceinline__ void cvt_store(float4 v, int idx, char* sm,
                                                 uint32_t hiOff) {
    uint32_t r  = (uint32_t)(idx >> 5);
    uint32_t cb = (uint32_t)((idx & 31) * 8);
    float h0 = bfr(v.x), h1 = bfr(v.y), h2 = bfr(v.z), h3 = bfr(v.w);
    uint32_t a = tswz(r, cb);
    *(uint2*)(sm + hiOff + a) = make_uint2(pack2(h0, h1), pack2(h2, h3));
    *(uint2*)(sm + hiOff + 32768 + a) = make_uint2(pack2(v.x - h0, v.y - h1),
                                                   pack2(v.z - h2, v.w - h3));
}

__global__ void __launch_bounds__(NTHR, 1)
fused_kernel(const float* __restrict__ x,
             const float* __restrict__ W1, const float* __restrict__ b1,
             const float* __restrict__ W2, const float* __restrict__ b2,
             const float* __restrict__ W3, const float* __restrict__ b3,
             float* __restrict__ out)
{
    extern __shared__ char sm[];
    const uint32_t sb = smem_u32(sm);
    const int tid   = threadIdx.x;
    const int wid   = tid >> 5;
    const int lane  = tid & 31;
    const int quad  = lane >> 2;
    const int four  = lane & 3;
    const int wband = wid >> 2;           // token band: rows wband*32 .. +31
    const int chgrp = wid & 3;            // channel group
    const int bb    = blockIdx.x;

    const float* xb = x + (size_t)bb * NTOK * DDIM;

    // ---- prologue: LDG chunk 0 -> regs; stage weights ----
    float4 xr[8];
    {
        const float4* s = (const float4*)xb;
#pragma unroll
        for (int i = 0; i < 8; ++i) xr[i] = s[tid + i * NTHR];
    }
    {
        const float2* w1 = (const float2*)W1;
#pragma unroll 4
        for (int i = 0; i < 16; ++i) {
            int idx = tid + i * NTHR;
            int n = idx >> 6, kp = idx & 63;
            float2 v = w1[idx];
            float hx = bfr(v.x), hy = bfr(v.y);
            uint32_t a = tswz(n, kp * 4);
            *(uint32_t*)(sm + S_W1HI + a) = pack2(hx, hy);
            *(uint32_t*)(sm + S_W1LO + a) = pack2(v.x - hx, v.y - hy);
        }
        const float2* w2 = (const float2*)W2;
#pragma unroll 4
        for (int i = 0; i < 8; ++i) {
            int idx = tid + i * NTHR;
            int n = idx >> 6, kp = idx & 63;
            float2 v = w2[idx];
            float hx = bfr(v.x), hy = bfr(v.y);
            uint32_t a = tswz(n, kp * 4);
            *(uint32_t*)(sm + S_W2HI + a) = pack2(hx, hy);
            *(uint32_t*)(sm + S_W2LO + a) = pack2(v.x - hx, v.y - hy);
        }
    }
    float bv = 0.f, cc = 0.f;     // per-channel bias + running carry (tid<128)
    if (tid < 128) {
        bv = b1[tid];
    } else if (tid < 192) {
        ((float*)(sm + S_B2))[tid - 128] = b2[tid - 128];
    } else if (tid < 256) {
        ((float*)(sm + S_W3))[tid - 192] = W3[tid - 192];
    }
    if (tid == 0) *(float*)(sm + S_B3) = b3[0];
    // convert chunk 0 into buf0
#pragma unroll
    for (int i = 0; i < 8; ++i) cvt_store(xr[i], tid + i * NTHR, sm, S_A0HI);
    __syncthreads();

    // ---- per-lane ldmatrix address pieces ----
    const uint32_t xrw  = (uint32_t)((lane & 7) << 4);
    const uint32_t aCol = (uint32_t)(((lane >> 4) & 1) * 16);
    const uint32_t bCol = (uint32_t)(((lane >> 3) & 1) * 16);
    const uint32_t aRowO = (uint32_t)(wband * 32 + (lane & 15)) * 256;   // + t*4096
    const uint32_t bRowO = (uint32_t)((lane & 7) + ((lane >> 4) & 1) * 8) * 256;
    const uint32_t w1Base = sb + S_W1HI + (uint32_t)(chgrp * 32) * 256 + bRowO;  // +32768 lo
    const uint32_t w2Base = sb + S_W2HI + (uint32_t)(chgrp * 16) * 256 + bRowO;  // +16384 lo
    float* scr = (float*)(sm + S_SCR);

    for (int c = 0; c < NCHUNK; ++c) {
        const uint32_t curHI = (c & 1) ? S_A1HI : S_A0HI;
        const uint32_t nxtHI = (c & 1) ? S_A0HI : S_A1HI;
        const uint32_t ahiB = sb + curHI + aRowO;
        const uint32_t aloB = ahiB + 32768;

        // ---- GEMM1: warp computes [32 tok][32 ch], fused 3-product split ----
        float acc[2][4][4];
#pragma unroll
        for (int t = 0; t < 2; ++t)
#pragma unroll
            for (int j = 0; j < 4; ++j) {
                acc[t][j][0] = 0.f; acc[t][j][1] = 0.f;
                acc[t][j][2] = 0.f; acc[t][j][3] = 0.f;
            }
#pragma unroll 2
        for (int ks = 0; ks < 8; ++ks) {
            uint32_t kc = (uint32_t)(ks * 32);
            uint32_t wk = (bCol | kc) ^ xrw;
            uint32_t ak = (aCol | kc) ^ xrw;
            uint32_t wh[8], wl[8];
            ldm4(w1Base + wk,                wh[0], wh[1], wh[2], wh[3]);
            ldm4(w1Base + 4096 + wk,         wh[4], wh[5], wh[6], wh[7]);
            ldm4(w1Base + 32768 + wk,        wl[0], wl[1], wl[2], wl[3]);
            ldm4(w1Base + 32768 + 4096 + wk, wl[4], wl[5], wl[6], wl[7]);
#pragma unroll
            for (int t = 0; t < 2; ++t) {
                uint32_t a0, a1, a2, a3, e0, e1, e2, e3;
                ldm4(ahiB + (uint32_t)(t * 4096) + ak, a0, a1, a2, a3);
                ldm4(aloB + (uint32_t)(t * 4096) + ak, e0, e1, e2, e3);
#pragma unroll
                for (int j = 0; j < 4; ++j) {
                    mma16816(acc[t][j], a0, a1, a2, a3, wh[2 * j], wh[2 * j + 1]);
                    mma16816(acc[t][j], e0, e1, e2, e3, wh[2 * j], wh[2 * j + 1]);
                    mma16816(acc[t][j], a0, a1, a2, a3, wl[2 * j], wl[2 * j + 1]);
                }
            }
        }

        // ---- issue LDG for next chunk (latency covered by scan+writeback) ----
        if (c + 1 < NCHUNK) {
            const float4* s = (const float4*)(xb + (size_t)(c + 1) * 128 * DDIM);
#pragma unroll
            for (int i = 0; i < 8; ++i) xr[i] = s[tid + i * NTHR];
        }

        // ---- scan over the warp's 32-token band (2 tiles, sequential carry) ----
        float ce[4] = {0.f, 0.f, 0.f, 0.f}, co[4] = {0.f, 0.f, 0.f, 0.f};
#pragma unroll
        for (int t = 0; t < 2; ++t) {
#pragma unroll
            for (int j = 0; j < 4; ++j) {
                scan_col(acc[t][j][0], acc[t][j][2], lane);
                scan_col(acc[t][j][1], acc[t][j][3], lane);
                acc[t][j][0] += ce[j]; acc[t][j][2] += ce[j];
                acc[t][j][1] += co[j]; acc[t][j][3] += co[j];
                ce[j] = __shfl_sync(0xffffffffu, acc[t][j][2], 28 + four);
                co[j] = __shfl_sync(0xffffffffu, acc[t][j][3], 28 + four);
            }
        }
        // band totals -> scr
        if (quad == 0) {
            float* tp = scr + wband * 128 + chgrp * 32 + 2 * four;
#pragma unroll
            for (int j = 0; j < 4; ++j)
                *(float2*)(tp + j * 8) = make_float2(ce[j], co[j]);
        }
        __syncthreads();                               // B1

        // ---- offsets in place: scr[w][ch] = cc + prefix(tot) + b1 ----
        if (tid < 128) {
            float a = cc;
#pragma unroll
            for (int w = 0; w < 4; ++w) {
                float tmp = scr[w * 128 + tid];
                scr[w * 128 + tid] = a + bv;
                a += tmp;
            }
            cc = a;
        }
        __syncthreads();                               // B2

        // ---- apply offsets + leaky, write H1 hi/lo (same buffer) ----
        {
            const float2* op = (const float2*)scr + wband * 64 + chgrp * 16 + four;
            const uint32_t r0 = (uint32_t)(wband * 32 + quad);
#pragma unroll
            for (int t = 0; t < 2; ++t) {
#pragma unroll
                for (int j = 0; j < 4; ++j) {
                    float2 o = op[j * 4];
                    float v0 = lrelu(acc[t][j][0] + o.x);
                    float v1 = lrelu(acc[t][j][1] + o.y);
                    float v2 = lrelu(acc[t][j][2] + o.x);
                    float v3 = lrelu(acc[t][j][3] + o.y);
                    float h0 = bfr(v0), h1 = bfr(v1), h2 = bfr(v2), h3 = bfr(v3);
                    uint32_t cb = (uint32_t)(chgrp * 64 + j * 16 + 4 * four);
                    uint32_t a0 = tswz(r0 + (uint32_t)(t * 16), cb);
                    *(uint32_t*)(sm + curHI + a0) = pack2(h0, h1);
                    *(uint32_t*)(sm + curHI + 32768 + a0) = pack2(v0 - h0, v1 - h1);
                    uint32_t a1 = a0 + 8 * 256;
                    *(uint32_t*)(sm + curHI + a1) = pack2(h2, h3);
                    *(uint32_t*)(sm + curHI + 32768 + a1) = pack2(v2 - h2, v3 - h3);
                }
            }
        }
        __syncthreads();                               // B3

        // ---- GEMM2 [32 tok][16 ch] with interleaved convert of next chunk ----
        float ac2[2][2][4];
#pragma unroll
        for (int t = 0; t < 2; ++t)
#pragma unroll
            for (int j = 0; j < 2; ++j) {
                ac2[t][j][0] = 0.f; ac2[t][j][1] = 0.f;
                ac2[t][j][2] = 0.f; ac2[t][j][3] = 0.f;
            }
#pragma unroll
        for (int ks = 0; ks < 8; ++ks) {
            uint32_t kc = (uint32_t)(ks * 32);
            uint32_t wk = (bCol | kc) ^ xrw;
            uint32_t ak = (aCol | kc) ^ xrw;
            uint32_t wh[4], wl[4];
            ldm4(w2Base + wk,         wh[0], wh[1], wh[2], wh[3]);
            ldm4(w2Base + 16384 + wk, wl[0], wl[1], wl[2], wl[3]);
#pragma unroll
            for (int t = 0; t < 2; ++t) {
                uint32_t a0, a1, a2, a3, e0, e1, e2, e3;
                ldm4(ahiB + (uint32_t)(t * 4096) + ak, a0, a1, a2, a3);
                ldm4(aloB + (uint32_t)(t * 4096) + ak, e0, e1, e2, e3);
#pragma unroll
                for (int j = 0; j < 2; ++j) {
                    mma16816(ac2[t][j], a0, a1, a2, a3, wh[2 * j], wh[2 * j + 1]);
                    mma16816(ac2[t][j], e0, e1, e2, e3, wh[2 * j], wh[2 * j + 1]);
                    mma16816(ac2[t][j], a0, a1, a2, a3, wl[2 * j], wl[2 * j + 1]);
                }
            }
            // interleaved convert: one float4 of x(c+1) per k-step
            if (c + 1 < NCHUNK)
                cvt_store(xr[ks], tid + ks * NTHR, sm, nxtHI);
        }

        // ---- epilogue: partial dot over warp's 16 channels -> scr ----
        {
            const float2* b2p = (const float2*)(sm + S_B2) + chgrp * 8 + four;
            const float2* w3p = (const float2*)(sm + S_W3) + chgrp * 8 + four;
            float2 bp0 = b2p[0], bp1 = b2p[4];
            float2 wp0 = w3p[0], wp1 = w3p[4];
            float* pt = scr + chgrp * 128 + wband * 32 + quad;
#pragma unroll
            for (int t = 0; t < 2; ++t) {
                float pl = lrelu(ac2[t][0][0] + bp0.x) * wp0.x
                         + lrelu(ac2[t][0][1] + bp0.y) * wp0.y
                         + lrelu(ac2[t][1][0] + bp1.x) * wp1.x
                         + lrelu(ac2[t][1][1] + bp1.y) * wp1.y;
                float ph = lrelu(ac2[t][0][2] + bp0.x) * wp0.x
                         + lrelu(ac2[t][0][3] + bp0.y) * wp0.y
                         + lrelu(ac2[t][1][2] + bp1.x) * wp1.x
                         + lrelu(ac2[t][1][3] + bp1.y) * wp1.y;
                pl += __shfl_xor_sync(0xffffffffu, pl, 1);
                pl += __shfl_xor_sync(0xffffffffu, pl, 2);
                ph += __shfl_xor_sync(0xffffffffu, ph, 1);
                ph += __shfl_xor_sync(0xffffffffu, ph, 2);
                if (four == 0) {
                    pt[t * 16] = pl;
                    pt[t * 16 + 8] = ph;
                }
            }
        }
        __syncthreads();                               // B4

        // ---- combine partials + b3 -> out ----
        if (tid < 128) {
            float s = scr[tid] + scr[128 + tid] + scr[256 + tid] + scr[384 + tid]
                    + *(const float*)(sm + S_B3);
            int g = c * 128 + tid;
            if (g > 0) out[(size_t)bb * NOUT + g - 1] = s;
        }
        __syncthreads();                               // B5 (scr reuse next chunk)
    }
}

// ---------------------------------------------------------------------------
extern "C" void kernel_launch(void* const* d_in, const int* in_sizes, int n_in,
                              void* d_out, int out_size) {
    const float* x  = (const float*)d_in[0];
    const float* W1 = (const float*)d_in[1];
    const float* b1 = (const float*)d_in[2];
    const float* W2 = (const float*)d_in[3];
    const float* b2 = (const float*)d_in[4];
    const float* W3 = (const float*)d_in[5];
    const float* b3 = (const float*)d_in[6];
    float* out = (float*)d_out;

    static bool attr_done = false;
    if (!attr_done) {
        cudaFuncSetAttribute(fused_kernel,
                             cudaFuncAttributeMaxDynamicSharedMemorySize,
                             SMEM_BYTES);
        attr_done = true;
    }

    fused_kernel<<<BATCH, NTHR, SMEM_BYTES>>>(x, W1, b1, W2, b2, W3, b3, out);
}

// round 10
// speedup vs baseline: 1.0800x; 1.0800x over previous
#include <cuda_runtime.h>
#include <cuda_bf16.h>
#include <stdint.h>
#include <string.h>

#define BATCH  512
#define NTOK   1024
#define DDIM   128
#define NCHUNK 8
#define NOUT   1023
#define NTHR   512

// ---------------- smem layout (bytes) ----------------
#define S_STAGE 0             // 57344: fp32 x chunk rows 0..111
#define S_AHI   57344         // 32768: A/H1 bf16 [128 rows][256B], XOR swizzle
#define S_ALO   90112         // 32768
#define S_W1HI  122880        // 32768
#define S_W1LO  155648        // 32768
#define S_W2HI  188416        // 16384
#define S_W2LO  204800        // 16384
#define S_TOT   221184        // 2048: band totals [4][128] f32
#define S_CCB   223232        // 1024: carry+b1, parity [2][128] f32
#define S_PT    224256        // 4096: epilogue partials, parity [2][4][128] f32
#define S_B2    228352        // 256
#define S_W3    228608        // 256
#define S_B3    228864        // 16
#define SMEM_BYTES 228880

static __device__ __forceinline__ uint32_t smem_u32(const void* p) {
    uint32_t a;
    asm("{ .reg .u64 t; cvta.to.shared.u64 t, %1; cvt.u32.u64 %0, t; }"
        : "=r"(a) : "l"(p));
    return a;
}
static __device__ __forceinline__ uint32_t tswz(uint32_t row, uint32_t cb) {
    return row * 256 + (cb ^ ((row & 7) << 4));
}
static __device__ __forceinline__ float bfr(float v) {
    return __bfloat162float(__float2bfloat16(v));
}
static __device__ __forceinline__ uint32_t pack2(float a, float b) {
    __nv_bfloat162 h = __floats2bfloat162_rn(a, b);
    uint32_t u;
    memcpy(&u, &h, 4);
    return u;
}
static __device__ __forceinline__ float lrelu(float v) {
    return v > 0.f ? v : 0.01f * v;
}
static __device__ __forceinline__ void ldm4(uint32_t addr, uint32_t& r0, uint32_t& r1,
                                            uint32_t& r2, uint32_t& r3) {
    asm volatile("ldmatrix.sync.aligned.m8n8.x4.shared.b16 {%0,%1,%2,%3}, [%4];"
                 : "=r"(r0), "=r"(r1), "=r"(r2), "=r"(r3) : "r"(addr));
}
static __device__ __forceinline__ void mma16816(float* d, uint32_t a0, uint32_t a1,
                                                uint32_t a2, uint32_t a3,
                                                uint32_t b0, uint32_t b1) {
    asm volatile("mma.sync.aligned.m16n8k16.row.col.f32.bf16.bf16.f32 "
                 "{%0,%1,%2,%3}, {%4,%5,%6,%7}, {%8,%9}, {%0,%1,%2,%3};"
                 : "+f"(d[0]), "+f"(d[1]), "+f"(d[2]), "+f"(d[3])
                 : "r"(a0), "r"(a1), "r"(a2), "r"(a3), "r"(b0), "r"(b1));
}
static __device__ __forceinline__ void scan_col(float& lo, float& hi, int lane) {
    float o;
    o = __shfl_up_sync(0xffffffffu, lo, 4);  if (lane >= 4)  lo += o;
    o = __shfl_up_sync(0xffffffffu, lo, 8);  if (lane >= 8)  lo += o;
    o = __shfl_up_sync(0xffffffffu, lo, 16); if (lane >= 16) lo += o;
    float tl = __shfl_sync(0xffffffffu, lo, 28 + (lane & 3));
    o = __shfl_up_sync(0xffffffffu, hi, 4);  if (lane >= 4)  hi += o;
    o = __shfl_up_sync(0xffffffffu, hi, 8);  if (lane >= 8)  hi += o;
    o = __shfl_up_sync(0xffffffffu, hi, 16); if (lane >= 16) hi += o;
    hi += tl;
}
// convert one float4 (index idx in [0,4096) over the 128x128 chunk) to hi/lo tiles
static __device__ __forceinline__ void cvt_store4(float4 v, int idx, char* sm) {
    uint32_t r  = (uint32_t)(idx >> 5);
    uint32_t cb = (uint32_t)((idx & 31) * 8);
    float h0 = bfr(v.x), h1 = bfr(v.y), h2 = bfr(v.z), h3 = bfr(v.w);
    uint32_t a = tswz(r, cb);
    *(uint2*)(sm + S_AHI + a) = make_uint2(pack2(h0, h1), pack2(h2, h3));
    *(uint2*)(sm + S_ALO + a) = make_uint2(pack2(v.x - h0, v.y - h1),
                                           pack2(v.z - h2, v.w - h3));
}

__global__ void __launch_bounds__(NTHR, 1)
fused_kernel(const float* __restrict__ x,
             const float* __restrict__ W1, const float* __restrict__ b1,
             const float* __restrict__ W2, const float* __restrict__ b2,
             const float* __restrict__ W3, const float* __restrict__ b3,
             float* __restrict__ out)
{
    extern __shared__ char sm[];
    const uint32_t sb = smem_u32(sm);
    const int tid   = threadIdx.x;
    const int wid   = tid >> 5;
    const int lane  = tid & 31;
    const int quad  = lane >> 2;
    const int four  = lane & 3;
    const int wband = wid >> 2;           // token band: rows wband*32 .. +31
    const int chgrp = wid & 3;            // channel group
    const int bb    = blockIdx.x;

    const float* xb = x + (size_t)bb * NTOK * DDIM;

    // ---- kick cp.async for chunk 0 (rows 0..111) + tail reg (112..127) ----
    float4 tl0;
    {
        const float4* s = (const float4*)xb;
#pragma unroll
        for (int i = 0; i < 7; ++i) {
            uint32_t d = sb + S_STAGE + (uint32_t)(tid + i * NTHR) * 16;
            asm volatile("cp.async.cg.shared.global [%0], [%1], 16;"
                         :: "r"(d), "l"(s + tid + i * NTHR) : "memory");
        }
        asm volatile("cp.async.commit_group;" ::: "memory");
        tl0 = s[3584 + tid];
    }

    // ---- stage weights: fp32 -> bf16 hi/lo swizzled tiles (float4 path) ----
    {
        const float4* w1 = (const float4*)W1;
#pragma unroll
        for (int i = 0; i < 8; ++i) {
            int idx = tid + i * NTHR;            // [0,4096)
            float4 v = w1[idx];
            uint32_t r  = (uint32_t)(idx >> 5);
            uint32_t cb = (uint32_t)((idx & 31) * 8);
            float h0 = bfr(v.x), h1 = bfr(v.y), h2 = bfr(v.z), h3 = bfr(v.w);
            uint32_t a = tswz(r, cb);
            *(uint2*)(sm + S_W1HI + a) = make_uint2(pack2(h0, h1), pack2(h2, h3));
            *(uint2*)(sm + S_W1LO + a) = make_uint2(pack2(v.x - h0, v.y - h1),
                                                    pack2(v.z - h2, v.w - h3));
        }
        const float4* w2 = (const float4*)W2;
#pragma unroll
        for (int i = 0; i < 4; ++i) {
            int idx = tid + i * NTHR;            // [0,2048)
            float4 v = w2[idx];
            uint32_t r  = (uint32_t)(idx >> 5);
            uint32_t cb = (uint32_t)((idx & 31) * 8);
            float h0 = bfr(v.x), h1 = bfr(v.y), h2 = bfr(v.z), h3 = bfr(v.w);
            uint32_t a = tswz(r, cb);
            *(uint2*)(sm + S_W2HI + a) = make_uint2(pack2(h0, h1), pack2(h2, h3));
            *(uint2*)(sm + S_W2LO + a) = make_uint2(pack2(v.x - h0, v.y - h1),
                                                    pack2(v.z - h2, v.w - h3));
        }
    }
    if (tid < 128) {
        ((float*)(sm + S_CCB))[tid] = b1[tid];   // CCB[0] = b1 (carry starts 0)
    } else if (tid < 192) {
        ((float*)(sm + S_B2))[tid - 128] = b2[tid - 128];
    } else if (tid < 256) {
        ((float*)(sm + S_W3))[tid - 192] = W3[tid - 192];
    }
    if (tid == 0) *(float*)(sm + S_B3) = b3[0];
    __syncthreads();   // weights + CCB[0] visible (covers pre-loop state)

    // ---- per-lane ldmatrix address pieces ----
    const uint32_t xr   = (uint32_t)((lane & 7) << 4);
    const uint32_t aCol = (uint32_t)(((lane >> 4) & 1) * 16);
    const uint32_t bCol = (uint32_t)(((lane >> 3) & 1) * 16);
    const uint32_t aRowO = (uint32_t)(wband * 32 + (lane & 15)) * 256;   // + t*4096
    const uint32_t bRowO = (uint32_t)((lane & 7) + ((lane >> 4) & 1) * 8) * 256;
    const uint32_t w1Base = sb + S_W1HI + (uint32_t)(chgrp * 32) * 256 + bRowO;  // +32768 lo
    const uint32_t w2Base = sb + S_W2HI + (uint32_t)(chgrp * 16) * 256 + bRowO;  // +16384 lo
    const uint32_t ahiB = sb + S_AHI + aRowO;
    const uint32_t aloB = sb + S_ALO + aRowO;

    for (int c = 0; c < NCHUNK; ++c) {
        const int p = c & 1;

        // ---- wait own cp.async; convert staged chunk -> A hi/lo (float4) ----
        asm volatile("cp.async.wait_group 0;" ::: "memory");
        {
            const float4* stg = (const float4*)(sm + S_STAGE);
#pragma unroll
            for (int i = 0; i < 7; ++i) {
                int idx = tid + i * NTHR;        // rows 0..111
                cvt_store4(stg[idx], idx, sm);
            }
            cvt_store4(tl0, 3584 + tid, sm);     // rows 112..127
        }
        __syncthreads();                         // B0: A tiles visible

        // ---- prefetch next chunk ----
        if (c + 1 < NCHUNK) {
            const float4* s = (const float4*)(xb + (size_t)(c + 1) * 128 * DDIM);
#pragma unroll
            for (int i = 0; i < 7; ++i) {
                uint32_t d = sb + S_STAGE + (uint32_t)(tid + i * NTHR) * 16;
                asm volatile("cp.async.cg.shared.global [%0], [%1], 16;"
                             :: "r"(d), "l"(s + tid + i * NTHR) : "memory");
            }
            asm volatile("cp.async.commit_group;" ::: "memory");
            tl0 = s[3584 + tid];
        }

        // ---- GEMM1: warp computes [32 tok][32 ch], fused 3-product split ----
        float acc[2][4][4];
#pragma unroll
        for (int t = 0; t < 2; ++t)
#pragma unroll
            for (int j = 0; j < 4; ++j) {
                acc[t][j][0] = 0.f; acc[t][j][1] = 0.f;
                acc[t][j][2] = 0.f; acc[t][j][3] = 0.f;
            }
#pragma unroll 2
        for (int ks = 0; ks < 8; ++ks) {
            uint32_t kc = (uint32_t)(ks * 32);
            uint32_t wk = (bCol | kc) ^ xr;
            uint32_t ak = (aCol | kc) ^ xr;
            uint32_t wh[8], wl[8];
            ldm4(w1Base + wk,                wh[0], wh[1], wh[2], wh[3]);
            ldm4(w1Base + 4096 + wk,         wh[4], wh[5], wh[6], wh[7]);
            ldm4(w1Base + 32768 + wk,        wl[0], wl[1], wl[2], wl[3]);
            ldm4(w1Base + 32768 + 4096 + wk, wl[4], wl[5], wl[6], wl[7]);
#pragma unroll
            for (int t = 0; t < 2; ++t) {
                uint32_t a0, a1, a2, a3, e0, e1, e2, e3;
                ldm4(ahiB + (uint32_t)(t * 4096) + ak, a0, a1, a2, a3);
                ldm4(aloB + (uint32_t)(t * 4096) + ak, e0, e1, e2, e3);
#pragma unroll
                for (int j = 0; j < 4; ++j) {
                    mma16816(acc[t][j], a0, a1, a2, a3, wh[2 * j], wh[2 * j + 1]);
                    mma16816(acc[t][j], e0, e1, e2, e3, wh[2 * j], wh[2 * j + 1]);
                    mma16816(acc[t][j], a0, a1, a2, a3, wl[2 * j], wl[2 * j + 1]);
                }
            }
        }

        // ---- scan over the warp's 32-token band (2 tiles, sequential carry) ----
        float ce[4] = {0.f, 0.f, 0.f, 0.f}, co[4] = {0.f, 0.f, 0.f, 0.f};
#pragma unroll
        for (int t = 0; t < 2; ++t) {
#pragma unroll
            for (int j = 0; j < 4; ++j) {
                scan_col(acc[t][j][0], acc[t][j][2], lane);
                scan_col(acc[t][j][1], acc[t][j][3], lane);
                acc[t][j][0] += ce[j]; acc[t][j][2] += ce[j];
                acc[t][j][1] += co[j]; acc[t][j][3] += co[j];
                ce[j] = __shfl_sync(0xffffffffu, acc[t][j][2], 28 + four);
                co[j] = __shfl_sync(0xffffffffu, acc[t][j][3], 28 + four);
            }
        }
        // band totals -> TOT
        if (quad == 0) {
            float* tp = (float*)(sm + S_TOT) + wband * 128 + chgrp * 32 + 2 * four;
#pragma unroll
            for (int j = 0; j < 4; ++j)
                *(float2*)(tp + j * 8) = make_float2(ce[j], co[j]);
        }
        __syncthreads();                         // B1: TOT visible, GEMM1 reads done

        // ---- per-warp offsets: off = CCB[p] + sum of lower-band totals ----
        float2 offv[4];
        {
            const float2* ccb = (const float2*)(sm + S_CCB + p * 512);
            const float2* tp2 = (const float2*)(sm + S_TOT);
#pragma unroll
            for (int j = 0; j < 4; ++j) {
                int cf = chgrp * 16 + 4 * j + four;
                float2 o = ccb[cf];
                for (int b2i = 0; b2i < wband; ++b2i) {
                    float2 t = tp2[b2i * 64 + cf];
                    o.x += t.x; o.y += t.y;
                }
                offv[j] = o;
            }
        }
        // band-3 warps update CCB for next chunk
        if (wband == 3) {
            int ch = chgrp * 32 + lane;
            const float* ccbC = (const float*)(sm + S_CCB + p * 512);
            float* ccbN = (float*)(sm + S_CCB + (1 - p) * 512);
            const float* tp = (const float*)(sm + S_TOT);
            ccbN[ch] = ccbC[ch] + tp[ch] + tp[128 + ch] + tp[256 + ch] + tp[384 + ch];
        }

        // ---- apply offsets + leaky, write H1 hi/lo (overwrite A tiles) ----
        {
            const uint32_t r0 = (uint32_t)(wband * 32 + quad);
#pragma unroll
            for (int t = 0; t < 2; ++t) {
#pragma unroll
                for (int j = 0; j < 4; ++j) {
                    float2 o = offv[j];
                    float v0 = lrelu(acc[t][j][0] + o.x);
                    float v1 = lrelu(acc[t][j][1] + o.y);
                    float v2 = lrelu(acc[t][j][2] + o.x);
                    float v3 = lrelu(acc[t][j][3] + o.y);
                    float h0 = bfr(v0), h1 = bfr(v1), h2 = bfr(v2), h3 = bfr(v3);
                    uint32_t cb = (uint32_t)(chgrp * 64 + j * 16 + 4 * four);
                    uint32_t a0 = tswz(r0 + (uint32_t)(t * 16), cb);
                    *(uint32_t*)(sm + S_AHI + a0) = pack2(h0, h1);
                    *(uint32_t*)(sm + S_ALO + a0) = pack2(v0 - h0, v1 - h1);
                    uint32_t a1 = a0 + 8 * 256;
                    *(uint32_t*)(sm + S_AHI + a1) = pack2(h2, h3);
                    *(uint32_t*)(sm + S_ALO + a1) = pack2(v2 - h2, v3 - h3);
                }
            }
        }
        __syncthreads();                         // B3: H1 + CCB[1-p] visible

        // ---- GEMM2: warp computes [32 tok][16 ch] ----
        float ac2[2][2][4];
#pragma unroll
        for (int t = 0; t < 2; ++t)
#pragma unroll
            for (int j = 0; j < 2; ++j) {
                ac2[t][j][0] = 0.f; ac2[t][j][1] = 0.f;
                ac2[t][j][2] = 0.f; ac2[t][j][3] = 0.f;
            }
#pragma unroll 2
        for (int ks = 0; ks < 8; ++ks) {
            uint32_t kc = (uint32_t)(ks * 32);
            uint32_t wk = (bCol | kc) ^ xr;
            uint32_t ak = (aCol | kc) ^ xr;
            uint32_t wh[4], wl[4];
            ldm4(w2Base + wk,         wh[0], wh[1], wh[2], wh[3]);
            ldm4(w2Base + 16384 + wk, wl[0], wl[1], wl[2], wl[3]);
#pragma unroll
            for (int t = 0; t < 2; ++t) {
                uint32_t a0, a1, a2, a3, e0, e1, e2, e3;
                ldm4(ahiB + (uint32_t)(t * 4096) + ak, a0, a1, a2, a3);
                ldm4(aloB + (uint32_t)(t * 4096) + ak, e0, e1, e2, e3);
#pragma unroll
                for (int j = 0; j < 2; ++j) {
                    mma16816(ac2[t][j], a0, a1, a2, a3, wh[2 * j], wh[2 * j + 1]);
                    mma16816(ac2[t][j], e0, e1, e2, e3, wh[2 * j], wh[2 * j + 1]);
                    mma16816(ac2[t][j], a0, a1, a2, a3, wl[2 * j], wl[2 * j + 1]);
                }
            }
        }

        // ---- epilogue: partial dot over warp's 16 channels -> PT[p] ----
        {
            const float2* b2p = (const float2*)(sm + S_B2) + chgrp * 8 + four;
            const float2* w3p = (const float2*)(sm + S_W3) + chgrp * 8 + four;
            float2 bp0 = b2p[0], bp1 = b2p[4];
            float2 wp0 = w3p[0], wp1 = w3p[4];
            float* pt = (float*)(sm + S_PT + p * 2048) + chgrp * 128 + wband * 32 + quad;
#pragma unroll
            for (int t = 0; t < 2; ++t) {
                float pl = lrelu(ac2[t][0][0] + bp0.x) * wp0.x
                         + lrelu(ac2[t][0][1] + bp0.y) * wp0.y
                         + lrelu(ac2[t][1][0] + bp1.x) * wp1.x
                         + lrelu(ac2[t][1][1] + bp1.y) * wp1.y;
                float ph = lrelu(ac2[t][0][2] + bp0.x) * wp0.x
                         + lrelu(ac2[t][0][3] + bp0.y) * wp0.y
                         + lrelu(ac2[t][1][2] + bp1.x) * wp1.x
                         + lrelu(ac2[t][1][3] + bp1.y) * wp1.y;
                pl += __shfl_xor_sync(0xffffffffu, pl, 1);
                pl += __shfl_xor_sync(0xffffffffu, pl, 2);
                ph += __shfl_xor_sync(0xffffffffu, ph, 1);
                ph += __shfl_xor_sync(0xffffffffu, ph, 2);
                if (four == 0) {
                    pt[t * 16] = pl;
                    pt[t * 16 + 8] = ph;
                }
            }
        }
        __syncthreads();                         // B4: PT[p] visible, GEMM2 done

        // ---- combine partials + b3 -> out (no trailing barrier: PT parity) ----
        if (tid < 128) {
            const float* pt = (const float*)(sm + S_PT + p * 2048);
            float s = pt[tid] + pt[128 + tid] + pt[256 + tid] + pt[384 + tid]
                    + *(const float*)(sm + S_B3);
            int g = c * 128 + tid;
            if (g > 0) out[(size_t)bb * NOUT + g - 1] = s;
        }
    }
}

// ---------------------------------------------------------------------------
extern "C" void kernel_launch(void* const* d_in, const int* in_sizes, int n_in,
                              void* d_out, int out_size) {
    const float* x  = (const float*)d_in[0];
    const float* W1 = (const float*)d_in[1];
    const float* b1 = (const float*)d_in[2];
    const float* W2 = (const float*)d_in[3];
    const float* b2 = (const float*)d_in[4];
    const float* W3 = (const float*)d_in[5];
    const float* b3 = (const float*)d_in[6];
    float* out = (float*)d_out;

    static bool attr_done = false;
    if (!attr_done) {
        cudaFuncSetAttribute(fused_kernel,
                             cudaFuncAttributeMaxDynamicSharedMemorySize,
                             SMEM_BYTES);
        attr_done = true;
    }

    fused_kernel<<<BATCH, NTHR, SMEM_BYTES>>>(x, W1, b1, W2, b2, W3, b3, out);
}

// round 11
// speedup vs baseline: 1.4464x; 1.3393x over previous
#include <cuda_runtime.h>
#include <cuda_fp16.h>
#include <stdint.h>
#include <string.h>

#define BATCH  512
#define NTOK   1024
#define DDIM   128
#define NCHUNK 8
#define NOUT   1023
#define NTHR   512

// ---------------- smem layout (bytes) ----------------
#define S_STAGE 0             // 57344: fp32 x chunk rows 0..111
#define S_A     57344         // 32768: A/H1 fp16 [128 rows][256B], XOR swizzle
#define S_W1HI  90112         // 32768
#define S_W1LO  122880        // 32768
#define S_W2HI  155648        // 16384
#define S_W2LO  172032        // 16384
#define S_TOT   188416        // 2048: band totals [4][128] f32
#define S_CCB   190464        // 1024: carry+b1, parity [2][128] f32
#define S_PT    191488        // 4096: epilogue partials, parity [2][4][128] f32
#define S_B2    195584        // 256
#define S_W3    195840        // 256
#define S_B3    196096        // 16
#define SMEM_BYTES 196112

static __device__ __forceinline__ uint32_t smem_u32(const void* p) {
    uint32_t a;
    asm("{ .reg .u64 t; cvta.to.shared.u64 t, %1; cvt.u32.u64 %0, t; }"
        : "=r"(a) : "l"(p));
    return a;
}
static __device__ __forceinline__ uint32_t tswz(uint32_t row, uint32_t cb) {
    return row * 256 + (cb ^ ((row & 7) << 4));
}
static __device__ __forceinline__ uint32_t pack2h(float a, float b) {
    __half2 h = __floats2half2_rn(a, b);
    uint32_t u;
    memcpy(&u, &h, 4);
    return u;
}
static __device__ __forceinline__ float lrelu(float v) {
    return v > 0.f ? v : 0.01f * v;
}
static __device__ __forceinline__ void ldm4(uint32_t addr, uint32_t& r0, uint32_t& r1,
                                            uint32_t& r2, uint32_t& r3) {
    asm volatile("ldmatrix.sync.aligned.m8n8.x4.shared.b16 {%0,%1,%2,%3}, [%4];"
                 : "=r"(r0), "=r"(r1), "=r"(r2), "=r"(r3) : "r"(addr));
}
static __device__ __forceinline__ void mma16816(float* d, uint32_t a0, uint32_t a1,
                                                uint32_t a2, uint32_t a3,
                                                uint32_t b0, uint32_t b1) {
    asm volatile("mma.sync.aligned.m16n8k16.row.col.f32.f16.f16.f32 "
                 "{%0,%1,%2,%3}, {%4,%5,%6,%7}, {%8,%9}, {%0,%1,%2,%3};"
                 : "+f"(d[0]), "+f"(d[1]), "+f"(d[2]), "+f"(d[3])
                 : "r"(a0), "r"(a1), "r"(a2), "r"(a3), "r"(b0), "r"(b1));
}
static __device__ __forceinline__ void scan_col(float& lo, float& hi, int lane) {
    float o;
    o = __shfl_up_sync(0xffffffffu, lo, 4);  if (lane >= 4)  lo += o;
    o = __shfl_up_sync(0xffffffffu, lo, 8);  if (lane >= 8)  lo += o;
    o = __shfl_up_sync(0xffffffffu, lo, 16); if (lane >= 16) lo += o;
    float tl = __shfl_sync(0xffffffffu, lo, 28 + (lane & 3));
    o = __shfl_up_sync(0xffffffffu, hi, 4);  if (lane >= 4)  hi += o;
    o = __shfl_up_sync(0xffffffffu, hi, 8);  if (lane >= 8)  hi += o;
    o = __shfl_up_sync(0xffffffffu, hi, 16); if (lane >= 16) hi += o;
    hi += tl;
}
// convert one float4 (index idx in [0,4096) over the 128x128 chunk) to fp16 tile
static __device__ __forceinline__ void cvt_store4(float4 v, int idx, char* sm) {
    uint32_t r  = (uint32_t)(idx >> 5);
    uint32_t cb = (uint32_t)((idx & 31) * 8);
    uint32_t a = tswz(r, cb);
    *(uint2*)(sm + S_A + a) = make_uint2(pack2h(v.x, v.y), pack2h(v.z, v.w));
}

__global__ void __launch_bounds__(NTHR, 1)
fused_kernel(const float* __restrict__ x,
             const float* __restrict__ W1, const float* __restrict__ b1,
             const float* __restrict__ W2, const float* __restrict__ b2,
             const float* __restrict__ W3, const float* __restrict__ b3,
             float* __restrict__ out)
{
    extern __shared__ char sm[];
    const uint32_t sb = smem_u32(sm);
    const int tid   = threadIdx.x;
    const int wid   = tid >> 5;
    const int lane  = tid & 31;
    const int quad  = lane >> 2;
    const int four  = lane & 3;
    const int wband = wid >> 2;           // token band: rows wband*32 .. +31
    const int chgrp = wid & 3;            // channel group
    const int bb    = blockIdx.x;

    const float* xb = x + (size_t)bb * NTOK * DDIM;

    // ---- kick cp.async for chunk 0 (rows 0..111) + tail reg (112..127) ----
    float4 tl0;
    {
        const float4* s = (const float4*)xb;
#pragma unroll
        for (int i = 0; i < 7; ++i) {
            uint32_t d = sb + S_STAGE + (uint32_t)(tid + i * NTHR) * 16;
            asm volatile("cp.async.cg.shared.global [%0], [%1], 16;"
                         :: "r"(d), "l"(s + tid + i * NTHR) : "memory");
        }
        asm volatile("cp.async.commit_group;" ::: "memory");
        tl0 = s[3584 + tid];
    }

    // ---- stage weights: fp32 -> fp16 hi/lo swizzled tiles ----
    {
        const float4* w1 = (const float4*)W1;
#pragma unroll
        for (int i = 0; i < 8; ++i) {
            int idx = tid + i * NTHR;            // [0,4096)
            float4 v = w1[idx];
            uint32_t r  = (uint32_t)(idx >> 5);
            uint32_t cb = (uint32_t)((idx & 31) * 8);
            float h0 = __half2float(__float2half_rn(v.x));
            float h1 = __half2float(__float2half_rn(v.y));
            float h2 = __half2float(__float2half_rn(v.z));
            float h3 = __half2float(__float2half_rn(v.w));
            uint32_t a = tswz(r, cb);
            *(uint2*)(sm + S_W1HI + a) = make_uint2(pack2h(h0, h1), pack2h(h2, h3));
            *(uint2*)(sm + S_W1LO + a) = make_uint2(pack2h(v.x - h0, v.y - h1),
                                                    pack2h(v.z - h2, v.w - h3));
        }
        const float4* w2 = (const float4*)W2;
#pragma unroll
        for (int i = 0; i < 4; ++i) {
            int idx = tid + i * NTHR;            // [0,2048)
            float4 v = w2[idx];
            uint32_t r  = (uint32_t)(idx >> 5);
            uint32_t cb = (uint32_t)((idx & 31) * 8);
            float h0 = __half2float(__float2half_rn(v.x));
            float h1 = __half2float(__float2half_rn(v.y));
            float h2 = __half2float(__float2half_rn(v.z));
            float h3 = __half2float(__float2half_rn(v.w));
            uint32_t a = tswz(r, cb);
            *(uint2*)(sm + S_W2HI + a) = make_uint2(pack2h(h0, h1), pack2h(h2, h3));
            *(uint2*)(sm + S_W2LO + a) = make_uint2(pack2h(v.x - h0, v.y - h1),
                                                    pack2h(v.z - h2, v.w - h3));
        }
    }
    if (tid < 128) {
        ((float*)(sm + S_CCB))[tid] = b1[tid];   // CCB[0] = b1 (carry starts 0)
    } else if (tid < 192) {
        ((float*)(sm + S_B2))[tid - 128] = b2[tid - 128];
    } else if (tid < 256) {
        ((float*)(sm + S_W3))[tid - 192] = W3[tid - 192];
    }
    if (tid == 0) *(float*)(sm + S_B3) = b3[0];
    __syncthreads();   // weights + CCB[0] visible

    // ---- per-lane ldmatrix address pieces ----
    const uint32_t xr   = (uint32_t)((lane & 7) << 4);
    const uint32_t aCol = (uint32_t)(((lane >> 4) & 1) * 16);
    const uint32_t bCol = (uint32_t)(((lane >> 3) & 1) * 16);
    const uint32_t aRowO = (uint32_t)(wband * 32 + (lane & 15)) * 256;   // + t*4096
    const uint32_t bRowO = (uint32_t)((lane & 7) + ((lane >> 4) & 1) * 8) * 256;
    const uint32_t w1hB = sb + S_W1HI + (uint32_t)(chgrp * 32) * 256 + bRowO;
    const uint32_t w1lB = w1hB + 32768;
    const uint32_t w2hB = sb + S_W2HI + (uint32_t)(chgrp * 16) * 256 + bRowO;
    const uint32_t w2lB = w2hB + 16384;
    const uint32_t aB   = sb + S_A + aRowO;

    for (int c = 0; c < NCHUNK; ++c) {
        const int p = c & 1;

        // ---- wait own cp.async; convert staged chunk -> A fp16 ----
        asm volatile("cp.async.wait_group 0;" ::: "memory");
        {
            const float4* stg = (const float4*)(sm + S_STAGE);
#pragma unroll
            for (int i = 0; i < 7; ++i) {
                int idx = tid + i * NTHR;        // rows 0..111
                cvt_store4(stg[idx], idx, sm);
            }
            cvt_store4(tl0, 3584 + tid, sm);     // rows 112..127
        }
        __syncthreads();                         // B0: A tile visible

        // ---- prefetch next chunk ----
        if (c + 1 < NCHUNK) {
            const float4* s = (const float4*)(xb + (size_t)(c + 1) * 128 * DDIM);
#pragma unroll
            for (int i = 0; i < 7; ++i) {
                uint32_t d = sb + S_STAGE + (uint32_t)(tid + i * NTHR) * 16;
                asm volatile("cp.async.cg.shared.global [%0], [%1], 16;"
                             :: "r"(d), "l"(s + tid + i * NTHR) : "memory");
            }
            asm volatile("cp.async.commit_group;" ::: "memory");
            tl0 = s[3584 + tid];
        }

        // ---- GEMM1: warp computes [32 tok][32 ch], 2-product fp16 split ----
        float acc[2][4][4];
#pragma unroll
        for (int t = 0; t < 2; ++t)
#pragma unroll
            for (int j = 0; j < 4; ++j) {
                acc[t][j][0] = 0.f; acc[t][j][1] = 0.f;
                acc[t][j][2] = 0.f; acc[t][j][3] = 0.f;
            }
#pragma unroll 2
        for (int ks = 0; ks < 8; ++ks) {
            uint32_t kc = (uint32_t)(ks * 32);
            uint32_t wk = (bCol | kc) ^ xr;
            uint32_t ak = (aCol | kc) ^ xr;
            uint32_t wh[8], wl[8];
            ldm4(w1hB + wk,        wh[0], wh[1], wh[2], wh[3]);
            ldm4(w1hB + 4096 + wk, wh[4], wh[5], wh[6], wh[7]);
            ldm4(w1lB + wk,        wl[0], wl[1], wl[2], wl[3]);
            ldm4(w1lB + 4096 + wk, wl[4], wl[5], wl[6], wl[7]);
#pragma unroll
            for (int t = 0; t < 2; ++t) {
                uint32_t a0, a1, a2, a3;
                ldm4(aB + (uint32_t)(t * 4096) + ak, a0, a1, a2, a3);
#pragma unroll
                for (int j = 0; j < 4; ++j) {
                    mma16816(acc[t][j], a0, a1, a2, a3, wh[2 * j], wh[2 * j + 1]);
                    mma16816(acc[t][j], a0, a1, a2, a3, wl[2 * j], wl[2 * j + 1]);
                }
            }
        }

        // ---- scan over the warp's 32-token band (2 tiles, sequential carry) ----
        float ce[4] = {0.f, 0.f, 0.f, 0.f}, co[4] = {0.f, 0.f, 0.f, 0.f};
#pragma unroll
        for (int t = 0; t < 2; ++t) {
#pragma unroll
            for (int j = 0; j < 4; ++j) {
                scan_col(acc[t][j][0], acc[t][j][2], lane);
                scan_col(acc[t][j][1], acc[t][j][3], lane);
                acc[t][j][0] += ce[j]; acc[t][j][2] += ce[j];
                acc[t][j][1] += co[j]; acc[t][j][3] += co[j];
                ce[j] = __shfl_sync(0xffffffffu, acc[t][j][2], 28 + four);
                co[j] = __shfl_sync(0xffffffffu, acc[t][j][3], 28 + four);
            }
        }
        // band totals -> TOT
        if (quad == 0) {
            float* tp = (float*)(sm + S_TOT) + wband * 128 + chgrp * 32 + 2 * four;
#pragma unroll
            for (int j = 0; j < 4; ++j)
                *(float2*)(tp + j * 8) = make_float2(ce[j], co[j]);
        }
        __syncthreads();                         // B1: TOT visible, GEMM1 reads done

        // ---- per-warp offsets: off = CCB[p] + sum of lower-band totals ----
        float2 offv[4];
        {
            const float2* ccb = (const float2*)(sm + S_CCB + p * 512);
            const float2* tp2 = (const float2*)(sm + S_TOT);
#pragma unroll
            for (int j = 0; j < 4; ++j) {
                int cf = chgrp * 16 + 4 * j + four;
                float2 o = ccb[cf];
                for (int b2i = 0; b2i < wband; ++b2i) {
                    float2 t = tp2[b2i * 64 + cf];
                    o.x += t.x; o.y += t.y;
                }
                offv[j] = o;
            }
        }
        // band-3 warps update CCB for next chunk
        if (wband == 3) {
            int ch = chgrp * 32 + lane;
            const float* ccbC = (const float*)(sm + S_CCB + p * 512);
            float* ccbN = (float*)(sm + S_CCB + (1 - p) * 512);
            const float* tp = (const float*)(sm + S_TOT);
            ccbN[ch] = ccbC[ch] + tp[ch] + tp[128 + ch] + tp[256 + ch] + tp[384 + ch];
        }

        // ---- apply offsets + leaky, write H1 fp16 (overwrite A tile) ----
        {
            const uint32_t r0 = (uint32_t)(wband * 32 + quad);
#pragma unroll
            for (int t = 0; t < 2; ++t) {
#pragma unroll
                for (int j = 0; j < 4; ++j) {
                    float2 o = offv[j];
                    float v0 = lrelu(acc[t][j][0] + o.x);
                    float v1 = lrelu(acc[t][j][1] + o.y);
                    float v2 = lrelu(acc[t][j][2] + o.x);
                    float v3 = lrelu(acc[t][j][3] + o.y);
                    uint32_t cb = (uint32_t)(chgrp * 64 + j * 16 + 4 * four);
                    uint32_t a0 = tswz(r0 + (uint32_t)(t * 16), cb);
                    *(uint32_t*)(sm + S_A + a0) = pack2h(v0, v1);
                    *(uint32_t*)(sm + S_A + a0 + 8 * 256) = pack2h(v2, v3);
                }
            }
        }
        __syncthreads();                         // B3: H1 + CCB[1-p] visible

        // ---- GEMM2: warp computes [32 tok][16 ch], 2-product split ----
        float ac2[2][2][4];
#pragma unroll
        for (int t = 0; t < 2; ++t)
#pragma unroll
            for (int j = 0; j < 2; ++j) {
                ac2[t][j][0] = 0.f; ac2[t][j][1] = 0.f;
                ac2[t][j][2] = 0.f; ac2[t][j][3] = 0.f;
            }
#pragma unroll 2
        for (int ks = 0; ks < 8; ++ks) {
            uint32_t kc = (uint32_t)(ks * 32);
            uint32_t wk = (bCol | kc) ^ xr;
            uint32_t ak = (aCol | kc) ^ xr;
            uint32_t wh[4], wl[4];
            ldm4(w2hB + wk, wh[0], wh[1], wh[2], wh[3]);
            ldm4(w2lB + wk, wl[0], wl[1], wl[2], wl[3]);
#pragma unroll
            for (int t = 0; t < 2; ++t) {
                uint32_t a0, a1, a2, a3;
                ldm4(aB + (uint32_t)(t * 4096) + ak, a0, a1, a2, a3);
#pragma unroll
                for (int j = 0; j < 2; ++j) {
                    mma16816(ac2[t][j], a0, a1, a2, a3, wh[2 * j], wh[2 * j + 1]);
                    mma16816(ac2[t][j], a0, a1, a2, a3, wl[2 * j], wl[2 * j + 1]);
                }
            }
        }

        // ---- epilogue: partial dot over warp's 16 channels -> PT[p] ----
        {
            const float2* b2p = (const float2*)(sm + S_B2) + chgrp * 8 + four;
            const float2* w3p = (const float2*)(sm + S_W3) + chgrp * 8 + four;
            float2 bp0 = b2p[0], bp1 = b2p[4];
            float2 wp0 = w3p[0], wp1 = w3p[4];
            float* pt = (float*)(sm + S_PT + p * 2048) + chgrp * 128 + wband * 32 + quad;
#pragma unroll
            for (int t = 0; t < 2; ++t) {
                float pl = lrelu(ac2[t][0][0] + bp0.x) * wp0.x
                         + lrelu(ac2[t][0][1] + bp0.y) * wp0.y
                         + lrelu(ac2[t][1][0] + bp1.x) * wp1.x
                         + lrelu(ac2[t][1][1] + bp1.y) * wp1.y;
                float ph = lrelu(ac2[t][0][2] + bp0.x) * wp0.x
                         + lrelu(ac2[t][0][3] + bp0.y) * wp0.y
                         + lrelu(ac2[t][1][2] + bp1.x) * wp1.x
                         + lrelu(ac2[t][1][3] + bp1.y) * wp1.y;
                pl += __shfl_xor_sync(0xffffffffu, pl, 1);
                pl += __shfl_xor_sync(0xffffffffu, pl, 2);
                ph += __shfl_xor_sync(0xffffffffu, ph, 1);
                ph += __shfl_xor_sync(0xffffffffu, ph, 2);
                if (four == 0) {
                    pt[t * 16] = pl;
                    pt[t * 16 + 8] = ph;
                }
            }
        }
        __syncthreads();                         // B4: PT[p] visible, GEMM2 done

        // ---- combine partials + b3 -> out (no trailing barrier: PT parity) ----
        if (tid < 128) {
            const float* pt = (const float*)(sm + S_PT + p * 2048);
            float s = pt[tid] + pt[128 + tid] + pt[256 + tid] + pt[384 + tid]
                    + *(const float*)(sm + S_B3);
            int g = c * 128 + tid;
            if (g > 0) out[(size_t)bb * NOUT + g - 1] = s;
        }
    }
}

// ---------------------------------------------------------------------------
extern "C" void kernel_launch(void* const* d_in, const int* in_sizes, int n_in,
                              void* d_out, int out_size) {
    const float* x  = (const float*)d_in[0];
    const float* W1 = (const float*)d_in[1];
    const float* b1 = (const float*)d_in[2];
    const float* W2 = (const float*)d_in[3];
    const float* b2 = (const float*)d_in[4];
    const float* W3 = (const float*)d_in[5];
    const float* b3 = (const float*)d_in[6];
    float* out = (float*)d_out;

    static bool attr_done = false;
    if (!attr_done) {
        cudaFuncSetAttribute(fused_kernel,
                             cudaFuncAttributeMaxDynamicSharedMemorySize,
                             SMEM_BYTES);
        attr_done = true;
    }

    fused_kernel<<<BATCH, NTHR, SMEM_BYTES>>>(x, W1, b1, W2, b2, W3, b3, out);
}

// round 12
// speedup vs baseline: 1.4727x; 1.0182x over previous
#include <cuda_runtime.h>
#include <cuda_fp16.h>
#include <stdint.h>
#include <string.h>

#define BATCH  512
#define NTOK   1024
#define DDIM   128
#define NCHUNK 8
#define NOUT   1023
#define NTHR   512

// ---------------- smem layout (bytes) ----------------
#define S_STAGE 0             // 57344: fp32 x chunk rows 0..111
#define S_A0    57344         // 32768: A/H1 fp16 [128 rows][256B], XOR swizzle
#define S_A1    90112         // 32768: second A buffer
#define S_W1HI  122880        // 32768
#define S_W1LO  155648        // 32768
#define S_W2HI  188416        // 16384
#define S_W2LO  204800        // 16384
#define S_TOT   221184        // 2048: band totals [4][128] f32
#define S_CCB   223232        // 1024: carry+b1, parity [2][128] f32
#define S_PT    224256        // 4096: epilogue partials, parity [2][4][128] f32
#define S_B2    228352        // 256
#define S_W3    228608        // 256
#define S_B3    228864        // 16
#define SMEM_BYTES 228880

static __device__ __forceinline__ uint32_t smem_u32(const void* p) {
    uint32_t a;
    asm("{ .reg .u64 t; cvta.to.shared.u64 t, %1; cvt.u32.u64 %0, t; }"
        : "=r"(a) : "l"(p));
    return a;
}
static __device__ __forceinline__ uint32_t tswz(uint32_t row, uint32_t cb) {
    return row * 256 + (cb ^ ((row & 7) << 4));
}
static __device__ __forceinline__ uint32_t pack2h(float a, float b) {
    __half2 h = __floats2half2_rn(a, b);
    uint32_t u;
    memcpy(&u, &h, 4);
    return u;
}
static __device__ __forceinline__ float lrelu(float v) {
    return v > 0.f ? v : 0.01f * v;
}
static __device__ __forceinline__ void ldm4(uint32_t addr, uint32_t& r0, uint32_t& r1,
                                            uint32_t& r2, uint32_t& r3) {
    asm volatile("ldmatrix.sync.aligned.m8n8.x4.shared.b16 {%0,%1,%2,%3}, [%4];"
                 : "=r"(r0), "=r"(r1), "=r"(r2), "=r"(r3) : "r"(addr));
}
static __device__ __forceinline__ void mma16816(float* d, uint32_t a0, uint32_t a1,
                                                uint32_t a2, uint32_t a3,
                                                uint32_t b0, uint32_t b1) {
    asm volatile("mma.sync.aligned.m16n8k16.row.col.f32.f16.f16.f32 "
                 "{%0,%1,%2,%3}, {%4,%5,%6,%7}, {%8,%9}, {%0,%1,%2,%3};"
                 : "+f"(d[0]), "+f"(d[1]), "+f"(d[2]), "+f"(d[3])
                 : "r"(a0), "r"(a1), "r"(a2), "r"(a3), "r"(b0), "r"(b1));
}
static __device__ __forceinline__ void scan_col(float& lo, float& hi, int lane) {
    float o;
    o = __shfl_up_sync(0xffffffffu, lo, 4);  if (lane >= 4)  lo += o;
    o = __shfl_up_sync(0xffffffffu, lo, 8);  if (lane >= 8)  lo += o;
    o = __shfl_up_sync(0xffffffffu, lo, 16); if (lane >= 16) lo += o;
    float tl = __shfl_sync(0xffffffffu, lo, 28 + (lane & 3));
    o = __shfl_up_sync(0xffffffffu, hi, 4);  if (lane >= 4)  hi += o;
    o = __shfl_up_sync(0xffffffffu, hi, 8);  if (lane >= 8)  hi += o;
    o = __shfl_up_sync(0xffffffffu, hi, 16); if (lane >= 16) hi += o;
    hi += tl;
}
// convert one float4 (index idx in [0,4096) over the 128x128 chunk) to fp16 tile
static __device__ __forceinline__ void cvt_store4(float4 v, int idx, char* sm,
                                                  uint32_t aOff) {
    uint32_t r  = (uint32_t)(idx >> 5);
    uint32_t cb = (uint32_t)((idx & 31) * 8);
    uint32_t a = tswz(r, cb);
    *(uint2*)(sm + aOff + a) = make_uint2(pack2h(v.x, v.y), pack2h(v.z, v.w));
}

__global__ void __launch_bounds__(NTHR, 1)
fused_kernel(const float* __restrict__ x,
             const float* __restrict__ W1, const float* __restrict__ b1,
             const float* __restrict__ W2, const float* __restrict__ b2,
             const float* __restrict__ W3, const float* __restrict__ b3,
             float* __restrict__ out)
{
    extern __shared__ char sm[];
    const uint32_t sb = smem_u32(sm);
    const int tid   = threadIdx.x;
    const int wid   = tid >> 5;
    const int lane  = tid & 31;
    const int quad  = lane >> 2;
    const int four  = lane & 3;
    const int wband = wid >> 2;           // token band: rows wband*32 .. +31
    const int chgrp = wid & 3;            // channel group
    const int bb    = blockIdx.x;

    const float* xb = x + (size_t)bb * NTOK * DDIM;

    // ---- prologue: cp.async chunk0 (rows 0..111) + tail reg ----
    float4 tl0;
    {
        const float4* s = (const float4*)xb;
#pragma unroll
        for (int i = 0; i < 7; ++i) {
            uint32_t d = sb + S_STAGE + (uint32_t)(tid + i * NTHR) * 16;
            asm volatile("cp.async.cg.shared.global [%0], [%1], 16;"
                         :: "r"(d), "l"(s + tid + i * NTHR) : "memory");
        }
        asm volatile("cp.async.commit_group;" ::: "memory");
        tl0 = s[3584 + tid];
    }

    // ---- stage weights: fp32 -> fp16 hi/lo swizzled tiles ----
    {
        const float4* w1 = (const float4*)W1;
#pragma unroll
        for (int i = 0; i < 8; ++i) {
            int idx = tid + i * NTHR;            // [0,4096)
            float4 v = w1[idx];
            uint32_t r  = (uint32_t)(idx >> 5);
            uint32_t cb = (uint32_t)((idx & 31) * 8);
            float h0 = __half2float(__float2half_rn(v.x));
            float h1 = __half2float(__float2half_rn(v.y));
            float h2 = __half2float(__float2half_rn(v.z));
            float h3 = __half2float(__float2half_rn(v.w));
            uint32_t a = tswz(r, cb);
            *(uint2*)(sm + S_W1HI + a) = make_uint2(pack2h(h0, h1), pack2h(h2, h3));
            *(uint2*)(sm + S_W1LO + a) = make_uint2(pack2h(v.x - h0, v.y - h1),
                                                    pack2h(v.z - h2, v.w - h3));
        }
        const float4* w2 = (const float4*)W2;
#pragma unroll
        for (int i = 0; i < 4; ++i) {
            int idx = tid + i * NTHR;            // [0,2048)
            float4 v = w2[idx];
            uint32_t r  = (uint32_t)(idx >> 5);
            uint32_t cb = (uint32_t)((idx & 31) * 8);
            float h0 = __half2float(__float2half_rn(v.x));
            float h1 = __half2float(__float2half_rn(v.y));
            float h2 = __half2float(__float2half_rn(v.z));
            float h3 = __half2float(__float2half_rn(v.w));
            uint32_t a = tswz(r, cb);
            *(uint2*)(sm + S_W2HI + a) = make_uint2(pack2h(h0, h1), pack2h(h2, h3));
            *(uint2*)(sm + S_W2LO + a) = make_uint2(pack2h(v.x - h0, v.y - h1),
                                                    pack2h(v.z - h2, v.w - h3));
        }
    }
    if (tid < 128) {
        ((float*)(sm + S_CCB))[tid] = b1[tid];   // CCB[0] = b1 (carry starts 0)
    } else if (tid < 192) {
        ((float*)(sm + S_B2))[tid - 128] = b2[tid - 128];
    } else if (tid < 256) {
        ((float*)(sm + S_W3))[tid - 192] = W3[tid - 192];
    }
    if (tid == 0) *(float*)(sm + S_B3) = b3[0];

    // ---- convert chunk0 -> A0 (own slots only), prefetch chunk1 ----
    asm volatile("cp.async.wait_group 0;" ::: "memory");
    {
        const float4* stg = (const float4*)(sm + S_STAGE);
#pragma unroll
        for (int i = 0; i < 7; ++i) {
            int idx = tid + i * NTHR;
            cvt_store4(stg[idx], idx, sm, S_A0);
        }
        cvt_store4(tl0, 3584 + tid, sm, S_A0);
    }
    {
        const float4* s = (const float4*)(xb + 128 * DDIM);
#pragma unroll
        for (int i = 0; i < 7; ++i) {
            uint32_t d = sb + S_STAGE + (uint32_t)(tid + i * NTHR) * 16;
            asm volatile("cp.async.cg.shared.global [%0], [%1], 16;"
                         :: "r"(d), "l"(s + tid + i * NTHR) : "memory");
        }
        asm volatile("cp.async.commit_group;" ::: "memory");
        tl0 = s[3584 + tid];
    }
    __syncthreads();   // A0 + weights + CCB[0] visible

    // ---- per-lane ldmatrix address pieces ----
    const uint32_t xr   = (uint32_t)((lane & 7) << 4);
    const uint32_t aCol = (uint32_t)(((lane >> 4) & 1) * 16);
    const uint32_t bCol = (uint32_t)(((lane >> 3) & 1) * 16);
    const uint32_t aRowO = (uint32_t)(wband * 32 + (lane & 15)) * 256;   // + t*4096
    const uint32_t bRowO = (uint32_t)((lane & 7) + ((lane >> 4) & 1) * 8) * 256;
    const uint32_t w1hB = sb + S_W1HI + (uint32_t)(chgrp * 32) * 256 + bRowO;
    const uint32_t w1lB = w1hB + 32768;
    const uint32_t w2hB = sb + S_W2HI + (uint32_t)(chgrp * 16) * 256 + bRowO;
    const uint32_t w2lB = w2hB + 16384;

    for (int c = 0; c < NCHUNK; ++c) {
        const int p = c & 1;
        const uint32_t aCur = p ? S_A1 : S_A0;
        const uint32_t aNxt = p ? S_A0 : S_A1;
        const uint32_t aB = sb + aCur + aRowO;

        // ---- GEMM1: warp computes [32 tok][32 ch], 2-product fp16 split ----
        float acc[2][4][4];
#pragma unroll
        for (int t = 0; t < 2; ++t)
#pragma unroll
            for (int j = 0; j < 4; ++j) {
                acc[t][j][0] = 0.f; acc[t][j][1] = 0.f;
                acc[t][j][2] = 0.f; acc[t][j][3] = 0.f;
            }
#pragma unroll 2
        for (int ks = 0; ks < 8; ++ks) {
            uint32_t kc = (uint32_t)(ks * 32);
            uint32_t wk = (bCol | kc) ^ xr;
            uint32_t ak = (aCol | kc) ^ xr;
            uint32_t wh[8], wl[8];
            ldm4(w1hB + wk,        wh[0], wh[1], wh[2], wh[3]);
            ldm4(w1hB + 4096 + wk, wh[4], wh[5], wh[6], wh[7]);
            ldm4(w1lB + wk,        wl[0], wl[1], wl[2], wl[3]);
            ldm4(w1lB + 4096 + wk, wl[4], wl[5], wl[6], wl[7]);
#pragma unroll
            for (int t = 0; t < 2; ++t) {
                uint32_t a0, a1, a2, a3;
                ldm4(aB + (uint32_t)(t * 4096) + ak, a0, a1, a2, a3);
#pragma unroll
                for (int j = 0; j < 4; ++j) {
                    mma16816(acc[t][j], a0, a1, a2, a3, wh[2 * j], wh[2 * j + 1]);
                    mma16816(acc[t][j], a0, a1, a2, a3, wl[2 * j], wl[2 * j + 1]);
                }
            }
        }

        // ---- scan over the warp's 32-token band (2 tiles, sequential carry) ----
        float ce[4] = {0.f, 0.f, 0.f, 0.f}, co[4] = {0.f, 0.f, 0.f, 0.f};
#pragma unroll
        for (int t = 0; t < 2; ++t) {
#pragma unroll
            for (int j = 0; j < 4; ++j) {
                scan_col(acc[t][j][0], acc[t][j][2], lane);
                scan_col(acc[t][j][1], acc[t][j][3], lane);
                acc[t][j][0] += ce[j]; acc[t][j][2] += ce[j];
                acc[t][j][1] += co[j]; acc[t][j][3] += co[j];
                ce[j] = __shfl_sync(0xffffffffu, acc[t][j][2], 28 + four);
                co[j] = __shfl_sync(0xffffffffu, acc[t][j][3], 28 + four);
            }
        }
        // band totals -> TOT
        if (quad == 0) {
            float* tp = (float*)(sm + S_TOT) + wband * 128 + chgrp * 32 + 2 * four;
#pragma unroll
            for (int j = 0; j < 4; ++j)
                *(float2*)(tp + j * 8) = make_float2(ce[j], co[j]);
        }
        __syncthreads();                         // B1: TOT visible, GEMM1 reads done

        // ---- per-warp offsets: off = CCB[p] + sum of lower-band totals ----
        float2 offv[4];
        {
            const float2* ccb = (const float2*)(sm + S_CCB + p * 512);
            const float2* tp2 = (const float2*)(sm + S_TOT);
#pragma unroll
            for (int j = 0; j < 4; ++j) {
                int cf = chgrp * 16 + 4 * j + four;
                float2 o = ccb[cf];
                for (int b2i = 0; b2i < wband; ++b2i) {
                    float2 t = tp2[b2i * 64 + cf];
                    o.x += t.x; o.y += t.y;
                }
                offv[j] = o;
            }
        }
        // band-3 warps update CCB for next chunk
        if (wband == 3) {
            int ch = chgrp * 32 + lane;
            const float* ccbC = (const float*)(sm + S_CCB + p * 512);
            float* ccbN = (float*)(sm + S_CCB + (1 - p) * 512);
            const float* tp = (const float*)(sm + S_TOT);
            ccbN[ch] = ccbC[ch] + tp[ch] + tp[128 + ch] + tp[256 + ch] + tp[384 + ch];
        }

        // ---- apply offsets + leaky, write H1 fp16 (overwrite A tile) ----
        {
            const uint32_t r0 = (uint32_t)(wband * 32 + quad);
#pragma unroll
            for (int t = 0; t < 2; ++t) {
#pragma unroll
                for (int j = 0; j < 4; ++j) {
                    float2 o = offv[j];
                    float v0 = lrelu(acc[t][j][0] + o.x);
                    float v1 = lrelu(acc[t][j][1] + o.y);
                    float v2 = lrelu(acc[t][j][2] + o.x);
                    float v3 = lrelu(acc[t][j][3] + o.y);
                    uint32_t cb = (uint32_t)(chgrp * 64 + j * 16 + 4 * four);
                    uint32_t a0 = tswz(r0 + (uint32_t)(t * 16), cb);
                    *(uint32_t*)(sm + aCur + a0) = pack2h(v0, v1);
                    *(uint32_t*)(sm + aCur + a0 + 8 * 256) = pack2h(v2, v3);
                }
            }
        }
        __syncthreads();                         // B3: H1 + CCB[1-p] visible

        // ---- GEMM2: warp computes [32 tok][16 ch], 2-product split ----
        float ac2[2][2][4];
#pragma unroll
        for (int t = 0; t < 2; ++t)
#pragma unroll
            for (int j = 0; j < 2; ++j) {
                ac2[t][j][0] = 0.f; ac2[t][j][1] = 0.f;
                ac2[t][j][2] = 0.f; ac2[t][j][3] = 0.f;
            }
#pragma unroll 2
        for (int ks = 0; ks < 8; ++ks) {
            uint32_t kc = (uint32_t)(ks * 32);
            uint32_t wk = (bCol | kc) ^ xr;
            uint32_t ak = (aCol | kc) ^ xr;
            uint32_t wh[4], wl[4];
            ldm4(w2hB + wk, wh[0], wh[1], wh[2], wh[3]);
            ldm4(w2lB + wk, wl[0], wl[1], wl[2], wl[3]);
#pragma unroll
            for (int t = 0; t < 2; ++t) {
                uint32_t a0, a1, a2, a3;
                ldm4(aB + (uint32_t)(t * 4096) + ak, a0, a1, a2, a3);
#pragma unroll
                for (int j = 0; j < 2; ++j) {
                    mma16816(ac2[t][j], a0, a1, a2, a3, wh[2 * j], wh[2 * j + 1]);
                    mma16816(ac2[t][j], a0, a1, a2, a3, wl[2 * j], wl[2 * j + 1]);
                }
            }
        }

        // ---- overlapped: convert chunk c+1 stage->A_next, prefetch c+2 ----
        if (c + 1 < NCHUNK) {
            asm volatile("cp.async.wait_group 0;" ::: "memory");
            const float4* stg = (const float4*)(sm + S_STAGE);
#pragma unroll
            for (int i = 0; i < 7; ++i) {
                int idx = tid + i * NTHR;
                cvt_store4(stg[idx], idx, sm, aNxt);
            }
            cvt_store4(tl0, 3584 + tid, sm, aNxt);
            if (c + 2 < NCHUNK) {
                const float4* s = (const float4*)(xb + (size_t)(c + 2) * 128 * DDIM);
#pragma unroll
                for (int i = 0; i < 7; ++i) {
                    uint32_t d = sb + S_STAGE + (uint32_t)(tid + i * NTHR) * 16;
                    asm volatile("cp.async.cg.shared.global [%0], [%1], 16;"
                                 :: "r"(d), "l"(s + tid + i * NTHR) : "memory");
                }
                asm volatile("cp.async.commit_group;" ::: "memory");
                tl0 = s[3584 + tid];
            }
        }

        // ---- epilogue: partial dot over warp's 16 channels -> PT[p] ----
        {
            const float2* b2p = (const float2*)(sm + S_B2) + chgrp * 8 + four;
            const float2* w3p = (const float2*)(sm + S_W3) + chgrp * 8 + four;
            float2 bp0 = b2p[0], bp1 = b2p[4];
            float2 wp0 = w3p[0], wp1 = w3p[4];
            float* pt = (float*)(sm + S_PT + p * 2048) + chgrp * 128 + wband * 32 + quad;
#pragma unroll
            for (int t = 0; t < 2; ++t) {
                float pl = lrelu(ac2[t][0][0] + bp0.x) * wp0.x
                         + lrelu(ac2[t][0][1] + bp0.y) * wp0.y
                         + lrelu(ac2[t][1][0] + bp1.x) * wp1.x
                         + lrelu(ac2[t][1][1] + bp1.y) * wp1.y;
                float ph = lrelu(ac2[t][0][2] + bp0.x) * wp0.x
                         + lrelu(ac2[t][0][3] + bp0.y) * wp0.y
                         + lrelu(ac2[t][1][2] + bp1.x) * wp1.x
                         + lrelu(ac2[t][1][3] + bp1.y) * wp1.y;
                pl += __shfl_xor_sync(0xffffffffu, pl, 1);
                pl += __shfl_xor_sync(0xffffffffu, pl, 2);
                ph += __shfl_xor_sync(0xffffffffu, ph, 1);
                ph += __shfl_xor_sync(0xffffffffu, ph, 2);
                if (four == 0) {
                    pt[t * 16] = pl;
                    pt[t * 16 + 8] = ph;
                }
            }
        }
        __syncthreads();                         // B4: PT[p] + A_next visible

        // ---- combine partials + b3 -> out (no trailing barrier: PT parity) ----
        if (tid < 128) {
            const float* pt = (const float*)(sm + S_PT + p * 2048);
            float s = pt[tid] + pt[128 + tid] + pt[256 + tid] + pt[384 + tid]
                    + *(const float*)(sm + S_B3);
            int g = c * 128 + tid;
            if (g > 0) out[(size_t)bb * NOUT + g - 1] = s;
        }
    }
}

// ---------------------------------------------------------------------------
extern "C" void kernel_launch(void* const* d_in, const int* in_sizes, int n_in,
                              void* d_out, int out_size) {
    const float* x  = (const float*)d_in[0];
    const float* W1 = (const float*)d_in[1];
    const float* b1 = (const float*)d_in[2];
    const float* W2 = (const float*)d_in[3];
    const float* b2 = (const float*)d_in[4];
    const float* W3 = (const float*)d_in[5];
    const float* b3 = (const float*)d_in[6];
    float* out = (float*)d_out;

    static bool attr_done = false;
    if (!attr_done) {
        cudaFuncSetAttribute(fused_kernel,
                             cudaFuncAttributeMaxDynamicSharedMemorySize,
                             SMEM_BYTES);
        attr_done = true;
    }

    fused_kernel<<<BATCH, NTHR, SMEM_BYTES>>>(x, W1, b1, W2, b2, W3, b3, out);
}

// round 13
// speedup vs baseline: 1.8621x; 1.2644x over previous
#include <cuda_runtime.h>
#include <cuda_fp16.h>
#include <stdint.h>
#include <string.h>

#define BATCH  512
#define NTOK   1024
#define DDIM   128
#define NCHUNK 8
#define NOUT   1023
#define NTHR   512

// ---------------- smem layout (bytes) ----------------
#define S_STAGE 0             // 57344: fp32 x chunk rows 0..111
#define S_A0    57344         // 32768: A/H1 fp16 [128 rows][256B], XOR swizzle
#define S_A1    90112         // 32768: second A buffer
#define S_W1    122880        // 32768: W1 fp16 single
#define S_W2    155648        // 16384: W2 fp16 single
#define S_TOT   172032        // 2048: band totals [4][128] f32
#define S_CCB   174080        // 1024: carry+b1, parity [2][128] f32
#define S_PT    175104        // 4096: epilogue partials, parity [2][4][128] f32
#define S_B2    179200        // 256
#define S_W3    179456        // 256
#define S_B3    179712        // 16
#define SMEM_BYTES 179728

static __device__ __forceinline__ uint32_t smem_u32(const void* p) {
    uint32_t a;
    asm("{ .reg .u64 t; cvta.to.shared.u64 t, %1; cvt.u32.u64 %0, t; }"
        : "=r"(a) : "l"(p));
    return a;
}
static __device__ __forceinline__ uint32_t tswz(uint32_t row, uint32_t cb) {
    return row * 256 + (cb ^ ((row & 7) << 4));
}
static __device__ __forceinline__ uint32_t pack2h(float a, float b) {
    __half2 h = __floats2half2_rn(a, b);
    uint32_t u;
    memcpy(&u, &h, 4);
    return u;
}
static __device__ __forceinline__ float lrelu(float v) {
    return v > 0.f ? v : 0.01f * v;
}
static __device__ __forceinline__ void ldm4(uint32_t addr, uint32_t& r0, uint32_t& r1,
                                            uint32_t& r2, uint32_t& r3) {
    asm volatile("ldmatrix.sync.aligned.m8n8.x4.shared.b16 {%0,%1,%2,%3}, [%4];"
                 : "=r"(r0), "=r"(r1), "=r"(r2), "=r"(r3) : "r"(addr));
}
static __device__ __forceinline__ void mma16816(float* d, uint32_t a0, uint32_t a1,
                                                uint32_t a2, uint32_t a3,
                                                uint32_t b0, uint32_t b1) {
    asm volatile("mma.sync.aligned.m16n8k16.row.col.f32.f16.f16.f32 "
                 "{%0,%1,%2,%3}, {%4,%5,%6,%7}, {%8,%9}, {%0,%1,%2,%3};"
                 : "+f"(d[0]), "+f"(d[1]), "+f"(d[2]), "+f"(d[3])
                 : "r"(a0), "r"(a1), "r"(a2), "r"(a3), "r"(b0), "r"(b1));
}
static __device__ __forceinline__ void scan_col(float& lo, float& hi, int lane) {
    float o;
    o = __shfl_up_sync(0xffffffffu, lo, 4);  if (lane >= 4)  lo += o;
    o = __shfl_up_sync(0xffffffffu, lo, 8);  if (lane >= 8)  lo += o;
    o = __shfl_up_sync(0xffffffffu, lo, 16); if (lane >= 16) lo += o;
    float tl = __shfl_sync(0xffffffffu, lo, 28 + (lane & 3));
    o = __shfl_up_sync(0xffffffffu, hi, 4);  if (lane >= 4)  hi += o;
    o = __shfl_up_sync(0xffffffffu, hi, 8);  if (lane >= 8)  hi += o;
    o = __shfl_up_sync(0xffffffffu, hi, 16); if (lane >= 16) hi += o;
    hi += tl;
}
// convert one float4 (index idx in [0,4096) over the 128x128 chunk) to fp16 tile
static __device__ __forceinline__ void cvt_store4(float4 v, int idx, char* sm,
                                                  uint32_t aOff) {
    uint32_t r  = (uint32_t)(idx >> 5);
    uint32_t cb = (uint32_t)((idx & 31) * 8);
    uint32_t a = tswz(r, cb);
    *(uint2*)(sm + aOff + a) = make_uint2(pack2h(v.x, v.y), pack2h(v.z, v.w));
}

__global__ void __launch_bounds__(NTHR, 1)
fused_kernel(const float* __restrict__ x,
             const float* __restrict__ W1, const float* __restrict__ b1,
             const float* __restrict__ W2, const float* __restrict__ b2,
             const float* __restrict__ W3, const float* __restrict__ b3,
             float* __restrict__ out)
{
    extern __shared__ char sm[];
    const uint32_t sb = smem_u32(sm);
    const int tid   = threadIdx.x;
    const int wid   = tid >> 5;
    const int lane  = tid & 31;
    const int quad  = lane >> 2;
    const int four  = lane & 3;
    const int wband = wid >> 2;           // token band: rows wband*32 .. +31
    const int chgrp = wid & 3;            // channel group
    const int bb    = blockIdx.x;

    const float* xb = x + (size_t)bb * NTOK * DDIM;

    // ---- prologue: cp.async chunk0 (rows 0..111) + tail reg ----
    float4 tl0;
    {
        const float4* s = (const float4*)xb;
#pragma unroll
        for (int i = 0; i < 7; ++i) {
            uint32_t d = sb + S_STAGE + (uint32_t)(tid + i * NTHR) * 16;
            asm volatile("cp.async.cg.shared.global [%0], [%1], 16;"
                         :: "r"(d), "l"(s + tid + i * NTHR) : "memory");
        }
        asm volatile("cp.async.commit_group;" ::: "memory");
        tl0 = s[3584 + tid];
    }

    // ---- stage weights: fp32 -> fp16 single swizzled tiles ----
    {
        const float4* w1 = (const float4*)W1;
#pragma unroll
        for (int i = 0; i < 8; ++i) {
            int idx = tid + i * NTHR;            // [0,4096)
            float4 v = w1[idx];
            uint32_t r  = (uint32_t)(idx >> 5);
            uint32_t cb = (uint32_t)((idx & 31) * 8);
            uint32_t a = tswz(r, cb);
            *(uint2*)(sm + S_W1 + a) = make_uint2(pack2h(v.x, v.y), pack2h(v.z, v.w));
        }
        const float4* w2 = (const float4*)W2;
#pragma unroll
        for (int i = 0; i < 4; ++i) {
            int idx = tid + i * NTHR;            // [0,2048)
            float4 v = w2[idx];
            uint32_t r  = (uint32_t)(idx >> 5);
            uint32_t cb = (uint32_t)((idx & 31) * 8);
            uint32_t a = tswz(r, cb);
            *(uint2*)(sm + S_W2 + a) = make_uint2(pack2h(v.x, v.y), pack2h(v.z, v.w));
        }
    }
    if (tid < 128) {
        ((float*)(sm + S_CCB))[tid] = b1[tid];   // CCB[0] = b1 (carry starts 0)
    } else if (tid < 192) {
        ((float*)(sm + S_B2))[tid - 128] = b2[tid - 128];
    } else if (tid < 256) {
        ((float*)(sm + S_W3))[tid - 192] = W3[tid - 192];
    }
    if (tid == 0) *(float*)(sm + S_B3) = b3[0];

    // ---- convert chunk0 -> A0 (own slots only), prefetch chunk1 ----
    asm volatile("cp.async.wait_group 0;" ::: "memory");
    {
        const float4* stg = (const float4*)(sm + S_STAGE);
#pragma unroll
        for (int i = 0; i < 7; ++i) {
            int idx = tid + i * NTHR;
            cvt_store4(stg[idx], idx, sm, S_A0);
        }
        cvt_store4(tl0, 3584 + tid, sm, S_A0);
    }
    {
        const float4* s = (const float4*)(xb + 128 * DDIM);
#pragma unroll
        for (int i = 0; i < 7; ++i) {
            uint32_t d = sb + S_STAGE + (uint32_t)(tid + i * NTHR) * 16;
            asm volatile("cp.async.cg.shared.global [%0], [%1], 16;"
                         :: "r"(d), "l"(s + tid + i * NTHR) : "memory");
        }
        asm volatile("cp.async.commit_group;" ::: "memory");
        tl0 = s[3584 + tid];
    }
    __syncthreads();   // A0 + weights + CCB[0] visible

    // ---- per-lane ldmatrix address pieces ----
    const uint32_t xr   = (uint32_t)((lane & 7) << 4);
    const uint32_t aCol = (uint32_t)(((lane >> 4) & 1) * 16);
    const uint32_t bCol = (uint32_t)(((lane >> 3) & 1) * 16);
    const uint32_t aRowO = (uint32_t)(wband * 32 + (lane & 15)) * 256;   // + t*4096
    const uint32_t bRowO = (uint32_t)((lane & 7) + ((lane >> 4) & 1) * 8) * 256;
    const uint32_t w1B = sb + S_W1 + (uint32_t)(chgrp * 32) * 256 + bRowO;
    const uint32_t w2B = sb + S_W2 + (uint32_t)(chgrp * 16) * 256 + bRowO;

    for (int c = 0; c < NCHUNK; ++c) {
        const int p = c & 1;
        const uint32_t aCur = p ? S_A1 : S_A0;
        const uint32_t aNxt = p ? S_A0 : S_A1;
        const uint32_t aB = sb + aCur + aRowO;

        // ---- GEMM1: warp computes [32 tok][32 ch], single fp16 product ----
        float acc[2][4][4];
#pragma unroll
        for (int t = 0; t < 2; ++t)
#pragma unroll
            for (int j = 0; j < 4; ++j) {
                acc[t][j][0] = 0.f; acc[t][j][1] = 0.f;
                acc[t][j][2] = 0.f; acc[t][j][3] = 0.f;
            }
#pragma unroll
        for (int ks = 0; ks < 8; ++ks) {
            uint32_t kc = (uint32_t)(ks * 32);
            uint32_t wk = (bCol | kc) ^ xr;
            uint32_t ak = (aCol | kc) ^ xr;
            uint32_t wh[8];
            ldm4(w1B + wk,        wh[0], wh[1], wh[2], wh[3]);
            ldm4(w1B + 4096 + wk, wh[4], wh[5], wh[6], wh[7]);
#pragma unroll
            for (int t = 0; t < 2; ++t) {
                uint32_t a0, a1, a2, a3;
                ldm4(aB + (uint32_t)(t * 4096) + ak, a0, a1, a2, a3);
#pragma unroll
                for (int j = 0; j < 4; ++j)
                    mma16816(acc[t][j], a0, a1, a2, a3, wh[2 * j], wh[2 * j + 1]);
            }
        }

        // ---- scan over the warp's 32-token band (2 tiles, sequential carry) ----
        float ce[4] = {0.f, 0.f, 0.f, 0.f}, co[4] = {0.f, 0.f, 0.f, 0.f};
#pragma unroll
        for (int t = 0; t < 2; ++t) {
#pragma unroll
            for (int j = 0; j < 4; ++j) {
                scan_col(acc[t][j][0], acc[t][j][2], lane);
                scan_col(acc[t][j][1], acc[t][j][3], lane);
                acc[t][j][0] += ce[j]; acc[t][j][2] += ce[j];
                acc[t][j][1] += co[j]; acc[t][j][3] += co[j];
                ce[j] = __shfl_sync(0xffffffffu, acc[t][j][2], 28 + four);
                co[j] = __shfl_sync(0xffffffffu, acc[t][j][3], 28 + four);
            }
        }
        // band totals -> TOT
        if (quad == 0) {
            float* tp = (float*)(sm + S_TOT) + wband * 128 + chgrp * 32 + 2 * four;
#pragma unroll
            for (int j = 0; j < 4; ++j)
                *(float2*)(tp + j * 8) = make_float2(ce[j], co[j]);
        }
        __syncthreads();                         // B1: TOT visible, GEMM1 reads done

        // ---- per-warp offsets: off = CCB[p] + sum of lower-band totals ----
        float2 offv[4];
        {
            const float2* ccb = (const float2*)(sm + S_CCB + p * 512);
            const float2* tp2 = (const float2*)(sm + S_TOT);
#pragma unroll
            for (int j = 0; j < 4; ++j) {
                int cf = chgrp * 16 + 4 * j + four;
                float2 o = ccb[cf];
                for (int b2i = 0; b2i < wband; ++b2i) {
                    float2 t = tp2[b2i * 64 + cf];
                    o.x += t.x; o.y += t.y;
                }
                offv[j] = o;
            }
        }
        // band-3 warps update CCB for next chunk
        if (wband == 3) {
            int ch = chgrp * 32 + lane;
            const float* ccbC = (const float*)(sm + S_CCB + p * 512);
            float* ccbN = (float*)(sm + S_CCB + (1 - p) * 512);
            const float* tp = (const float*)(sm + S_TOT);
            ccbN[ch] = ccbC[ch] + tp[ch] + tp[128 + ch] + tp[256 + ch] + tp[384 + ch];
        }

        // ---- apply offsets + leaky, write H1 fp16 (overwrite A tile) ----
        {
            const uint32_t r0 = (uint32_t)(wband * 32 + quad);
#pragma unroll
            for (int t = 0; t < 2; ++t) {
#pragma unroll
                for (int j = 0; j < 4; ++j) {
                    float2 o = offv[j];
                    float v0 = lrelu(acc[t][j][0] + o.x);
                    float v1 = lrelu(acc[t][j][1] + o.y);
                    float v2 = lrelu(acc[t][j][2] + o.x);
                    float v3 = lrelu(acc[t][j][3] + o.y);
                    uint32_t cb = (uint32_t)(chgrp * 64 + j * 16 + 4 * four);
                    uint32_t a0 = tswz(r0 + (uint32_t)(t * 16), cb);
                    *(uint32_t*)(sm + aCur + a0) = pack2h(v0, v1);
                    *(uint32_t*)(sm + aCur + a0 + 8 * 256) = pack2h(v2, v3);
                }
            }
        }
        __syncthreads();                         // B3: H1 + CCB[1-p] visible

        // ---- GEMM2: warp computes [32 tok][16 ch], single fp16 product ----
        float ac2[2][2][4];
#pragma unroll
        for (int t = 0; t < 2; ++t)
#pragma unroll
            for (int j = 0; j < 2; ++j) {
                ac2[t][j][0] = 0.f; ac2[t][j][1] = 0.f;
                ac2[t][j][2] = 0.f; ac2[t][j][3] = 0.f;
            }
#pragma unroll
        for (int ks = 0; ks < 8; ++ks) {
            uint32_t kc = (uint32_t)(ks * 32);
            uint32_t wk = (bCol | kc) ^ xr;
            uint32_t ak = (aCol | kc) ^ xr;
            uint32_t wh[4];
            ldm4(w2B + wk, wh[0], wh[1], wh[2], wh[3]);
#pragma unroll
            for (int t = 0; t < 2; ++t) {
                uint32_t a0, a1, a2, a3;
                ldm4(aB + (uint32_t)(t * 4096) + ak, a0, a1, a2, a3);
#pragma unroll
                for (int j = 0; j < 2; ++j)
                    mma16816(ac2[t][j], a0, a1, a2, a3, wh[2 * j], wh[2 * j + 1]);
            }
        }

        // ---- overlapped: convert chunk c+1 stage->A_next, prefetch c+2 ----
        if (c + 1 < NCHUNK) {
            asm volatile("cp.async.wait_group 0;" ::: "memory");
            const float4* stg = (const float4*)(sm + S_STAGE);
#pragma unroll
            for (int i = 0; i < 7; ++i) {
                int idx = tid + i * NTHR;
                cvt_store4(stg[idx], idx, sm, aNxt);
            }
            cvt_store4(tl0, 3584 + tid, sm, aNxt);
            if (c + 2 < NCHUNK) {
                const float4* s = (const float4*)(xb + (size_t)(c + 2) * 128 * DDIM);
#pragma unroll
                for (int i = 0; i < 7; ++i) {
                    uint32_t d = sb + S_STAGE + (uint32_t)(tid + i * NTHR) * 16;
                    asm volatile("cp.async.cg.shared.global [%0], [%1], 16;"
                                 :: "r"(d), "l"(s + tid + i * NTHR) : "memory");
                }
                asm volatile("cp.async.commit_group;" ::: "memory");
                tl0 = s[3584 + tid];
            }
        }

        // ---- epilogue: partial dot over warp's 16 channels -> PT[p] ----
        {
            const float2* b2p = (const float2*)(sm + S_B2) + chgrp * 8 + four;
            const float2* w3p = (const float2*)(sm + S_W3) + chgrp * 8 + four;
            float2 bp0 = b2p[0], bp1 = b2p[4];
            float2 wp0 = w3p[0], wp1 = w3p[4];
            float* pt = (float*)(sm + S_PT + p * 2048) + chgrp * 128 + wband * 32 + quad;
#pragma unroll
            for (int t = 0; t < 2; ++t) {
                float pl = lrelu(ac2[t][0][0] + bp0.x) * wp0.x
                         + lrelu(ac2[t][0][1] + bp0.y) * wp0.y
                         + lrelu(ac2[t][1][0] + bp1.x) * wp1.x
                         + lrelu(ac2[t][1][1] + bp1.y) * wp1.y;
                float ph = lrelu(ac2[t][0][2] + bp0.x) * wp0.x
                         + lrelu(ac2[t][0][3] + bp0.y) * wp0.y
                         + lrelu(ac2[t][1][2] + bp1.x) * wp1.x
                         + lrelu(ac2[t][1][3] + bp1.y) * wp1.y;
                pl += __shfl_xor_sync(0xffffffffu, pl, 1);
                pl += __shfl_xor_sync(0xffffffffu, pl, 2);
                ph += __shfl_xor_sync(0xffffffffu, ph, 1);
                ph += __shfl_xor_sync(0xffffffffu, ph, 2);
                if (four == 0) {
                    pt[t * 16] = pl;
                    pt[t * 16 + 8] = ph;
                }
            }
        }
        __syncthreads();                         // B4: PT[p] + A_next visible

        // ---- combine partials + b3 -> out (no trailing barrier: PT parity) ----
        if (tid < 128) {
            const float* pt = (const float*)(sm + S_PT + p * 2048);
            float s = pt[tid] + pt[128 + tid] + pt[256 + tid] + pt[384 + tid]
                    + *(const float*)(sm + S_B3);
            int g = c * 128 + tid;
            if (g > 0) out[(size_t)bb * NOUT + g - 1] = s;
        }
    }
}

// ---------------------------------------------------------------------------
extern "C" void kernel_launch(void* const* d_in, const int* in_sizes, int n_in,
                              void* d_out, int out_size) {
    const float* x  = (const float*)d_in[0];
    const float* W1 = (const float*)d_in[1];
    const float* b1 = (const float*)d_in[2];
    const float* W2 = (const float*)d_in[3];
    const float* b2 = (const float*)d_in[4];
    const float* W3 = (const float*)d_in[5];
    const float* b3 = (const float*)d_in[6];
    float* out = (float*)d_out;

    static bool attr_done = false;
    if (!attr_done) {
        cudaFuncSetAttribute(fused_kernel,
                             cudaFuncAttributeMaxDynamicSharedMemorySize,
                             SMEM_BYTES);
        attr_done = true;
    }

    fused_kernel<<<BATCH, NTHR, SMEM_BYTES>>>(x, W1, b1, W2, b2, W3, b3, out);
}